// round 8
// baseline (speedup 1.0000x reference)
#include <cuda_runtime.h>
#include <math.h>

#define NB 2
#define CXC 64
#define CYC 128
#define CO  64
#define DD  16
#define HH  64
#define WW  64
#define PX  (DD*HH*WW)    /* 65536 */
#define PY  (8*32*32)     /* 8192  */

// packed f32x2 FMA (Blackwell): one instr = 2 fp32 FMA
#define FMA2(acc, a, b) asm("fma.rn.f32x2 %0, %1, %2, %0;" : "+l"(acc) : "l"(a), "l"(b))

union F2U { float2 f; unsigned long long u; };
union F4U { float4 f; unsigned long long u[2]; };

// ---------------- scratch (device globals; no allocation) ----------------
__device__ float g_xmean[NB*CXC];
__device__ float g_w1[NB*64*180];                // folded x-path weights, dup-pair layout
__device__ float g_hf[NB*CO*PY];                 // 4 MB
__device__ float g_hfup[(size_t)NB*CO*PX];       // 33 MB
__device__ float g_flowp[16][NB*3*PX];           // partial flows per channel-group
__device__ float g_flow[NB*3*PX];                // summed flow
__device__ float g_yT[(size_t)NB*PY*CYC];        // 8 MB  y transposed to [n][p][c]

// ===== K1 (fused): hf 1x1 conv  |  xmean  |  y transpose ====================
__global__ void k_pre(const float* __restrict__ y,
                      const float* __restrict__ wdh,
                      const float* __restrict__ x) {
    __shared__ float sh[2112];
    int b = blockIdx.x;
    int tid = threadIdx.x;                       // 256

    if (b < 256) {
        int n  = b >> 7;
        int r  = b & 127;
        int og = r >> 5;
        int pb = r & 31;
        float (*wT)[16] = (float(*)[16])sh;      // wT[i][o_local]
        for (int idx = tid; idx < 128*16; idx += 256) {
            int ol = idx >> 7, i = idx & 127;
            wT[i][ol] = wdh[(og*16 + ol)*128 + i];
        }
        __syncthreads();
        int p = pb*256 + tid;
        const float* yp = y + (size_t)n*CYC*PY + p;
        float acc[16];
        #pragma unroll
        for (int o = 0; o < 16; o++) acc[o] = 0.f;
        for (int i = 0; i < 128; i++) {
            float v = yp[(size_t)i*PY];
            #pragma unroll
            for (int o4 = 0; o4 < 4; o4++) {
                float4 w4 = *(const float4*)&wT[i][o4*4];
                acc[o4*4+0] = fmaf(w4.x, v, acc[o4*4+0]);
                acc[o4*4+1] = fmaf(w4.y, v, acc[o4*4+1]);
                acc[o4*4+2] = fmaf(w4.z, v, acc[o4*4+2]);
                acc[o4*4+3] = fmaf(w4.w, v, acc[o4*4+3]);
            }
        }
        float* op = g_hf + (size_t)(n*CO + og*16)*PY + p;
        #pragma unroll
        for (int o = 0; o < 16; o++) op[(size_t)o*PY] = acc[o];
    } else if (b < 384) {
        int nc = b - 256;
        const float4* p4 = (const float4*)(x + (size_t)nc * PX);
        float s = 0.f;
        #pragma unroll 4
        for (int i = tid; i < PX/4; i += 256) {
            float4 v = p4[i];
            s += (v.x + v.y) + (v.z + v.w);
        }
        #pragma unroll
        for (int o = 16; o > 0; o >>= 1) s += __shfl_xor_sync(0xffffffffu, s, o);
        if ((tid & 31) == 0) sh[tid >> 5] = s;
        __syncthreads();
        if (tid < 8) {
            float t = sh[tid];
            #pragma unroll
            for (int o = 4; o > 0; o >>= 1) t += __shfl_xor_sync(0xffu, t, o, 8);
            if (tid == 0) g_xmean[nc] = t * (1.f / PX);
        }
    } else {
        int bb = b - 384;                        // 0..2047
        int n  = bb >> 10;
        int r  = bb & 1023;
        int pt = r >> 2;                         // 0..255
        int ct = r & 3;                          // 0..3
        int tx = tid & 31, ty = tid >> 5;        // ty 0..7
        const float* yb = y + (size_t)n*CYC*PY;
        #pragma unroll
        for (int k = 0; k < 4; k++) {
            int cl = ty + k*8;
            sh[cl*33 + tx] = yb[(size_t)(ct*32 + cl)*PY + pt*32 + tx];
        }
        __syncthreads();
        float* ob = g_yT + ((size_t)n*PY)*CYC;
        #pragma unroll
        for (int k = 0; k < 4; k++) {
            int pl = ty + k*8;
            ob[(size_t)(pt*32 + pl)*CYC + ct*32 + tx] = sh[tx*33 + pl];
        }
    }
}

// ---- K2: fold SE attention + 1x1 conv + flow-conv low half into W1_n ----
// dup-pair layout: [n][i][row(kd*3+kh)][20], pair j=(kw*3+o3) at floats 2j,2j+1
__global__ void k_prep(const float* __restrict__ wdl,
                       const float* __restrict__ wa,
                       const float* __restrict__ wc,
                       const float* __restrict__ wflow) {
    int n = blockIdx.x, t = threadIdx.x;     // 256 threads
    __shared__ float xm[64], pooled[64], scale[64];
    __shared__ float M[64][64];
    if (t < 64) xm[t] = g_xmean[n*64 + t];
    __syncthreads();
    if (t < 64) {
        float s = 0.f;
        for (int i = 0; i < 64; i++) s += wdl[t*64 + i] * xm[i];
        pooled[t] = s;
    }
    __syncthreads();
    if (t < 64) {
        float a = 0.f;
        for (int i = 0; i < 64; i++) a += wa[t*64 + i] * pooled[i];
        scale[t] = 1.f + 1.f / (1.f + expf(-a));
    }
    __syncthreads();
    for (int idx = t; idx < 4096; idx += 256) {
        int o = idx >> 6, i = idx & 63;
        float acc = 0.f;
        for (int c = 0; c < 64; c++) acc += wc[o*64 + c] * scale[c] * wdl[c*64 + i];
        M[o][i] = acc;
    }
    __syncthreads();
    for (int idx = t; idx < 64*81; idx += 256) {
        int i = idx / 81; int r = idx % 81; int tap = r / 3; int o3 = r % 3;
        float acc = 0.f;
        for (int c = 0; c < 64; c++)
            acc += wflow[o3*(128*27) + (64 + c)*27 + tap] * M[c][i];
        int kd = tap/9, kh = (tap/3)%3, kw = tap%3;
        float* dst = g_w1 + (size_t)(n*64 + i)*180 + (kd*3 + kh)*20 + 2*(kw*3 + o3);
        dst[0] = acc; dst[1] = acc;
    }
}

// ------ K3: trilinear upsample, 4 outputs/thread, shared source columns ----
__global__ void k_up() {
    int t = blockIdx.x*256 + threadIdx.x;    // over NB*CO*16*64*16
    int wg = (t & 15) << 2;                  // w start: 0,4,...,60
    int h  = (t >> 4) & 63;
    int d  = (t >> 10) & 15;
    int slab = t >> 14;                      // n*CO + c
    const float* hp = g_hf + (size_t)slab * PY;
    float ph = h * (31.f/63.f);
    float pd = d * (7.f/15.f);
    int h0 = (int)ph; float fh = ph - (float)h0; int h1 = min(h0 + 1, 31);
    int d0 = (int)pd; float fd = pd - (float)d0; int d1 = min(d0 + 1, 7);
    int xbase = (int)(wg * (31.f/63.f));
    const float* p00 = hp + (d0*32 + h0)*32;
    const float* p01 = hp + (d0*32 + h1)*32;
    const float* p10 = hp + (d1*32 + h0)*32;
    const float* p11 = hp + (d1*32 + h1)*32;
    float V[4];
    #pragma unroll
    for (int c2 = 0; c2 < 4; c2++) {
        int xc = min(xbase + c2, 31);
        float v00 = __ldg(p00 + xc), v01 = __ldg(p01 + xc);
        float v10 = __ldg(p10 + xc), v11 = __ldg(p11 + xc);
        float a = v00 + (v01 - v00)*fh;
        float b2 = v10 + (v11 - v10)*fh;
        V[c2] = a + (b2 - a)*fd;
    }
    float4 ov;
    float* po = (float*)&ov;
    #pragma unroll
    for (int i = 0; i < 4; i++) {
        float pw = (wg + i) * (31.f/63.f);
        int x0 = (int)pw; float fx = pw - (float)x0;
        int k = x0 - xbase;
        float va = (k == 0) ? V[0] : ((k == 1) ? V[1] : V[2]);
        float vb = (k == 0) ? V[1] : ((k == 1) ? V[2] : V[3]);
        po[i] = va + (vb - va)*fx;
    }
    *(float4*)(g_hfup + (size_t)slab*PX + ((d << 6) + h)*64 + wg) = ov;
}

// ------------- K4: 3x3x3 conv, f32x2, dz=2 x w=8 per thread ----------------
// block 128 = (tx 8, ty 16): outputs d0..d0+1, h0..h0+15, w 0..63
// smem tile 4 x 18 x 72 (gx stored at gx+4; idx 3 and 68 permanent zeros).
// Weights pre-duplicated in smem; WP register double-buffer across zz.
#define TROW 72
#define TYD  18
#define TZD  4
#define TSIZE (TZD*TYD*TROW)   /* 5184 */
#define GC 8                   /* channels per group */
__global__ void __launch_bounds__(128) k_conv3(const float* __restrict__ x,
                                               const float* __restrict__ wflow) {
    __shared__ __align__(16) float tile[2][TSIZE];
    __shared__ __align__(16) float wsm[GC*180];
    __shared__ int rowoff[TZD*TYD];
    int bz = blockIdx.z;
    int n = bz >> 4, g = bz & 15;
    int d0 = blockIdx.y * 2;
    int h0 = blockIdx.x * 16;
    int tid = threadIdx.x;                 // 0..127
    int tx = tid & 7, ty = tid >> 3;       // ty 0..15

    const float* inb = (g < 8) ? (x + (size_t)(n*64 + g*GC)*PX)
                               : (g_hfup + (size_t)(n*64 + (g-8)*GC)*PX);
    // stage weights: dup-pair layout [ch][row(kd*3+kh)][20]
    if (g < 8) {
        const float* src = g_w1 + (size_t)(n*64 + g*GC)*180;
        for (int idx = tid; idx < GC*180; idx += 128) wsm[idx] = src[idx];
    } else {
        int cbase = (g - 8)*GC;
        for (int idx = tid; idx < GC*81; idx += 128) {
            int ch = idx / 81; int r = idx % 81; int tap = r / 3; int o = r % 3;
            int kd = tap/9, kh = (tap/3)%3, kw = tap%3;
            float v = wflow[o*(128*27) + (cbase + ch)*27 + tap];
            int dst = ch*180 + (kd*3 + kh)*20 + 2*(kw*3 + o);
            wsm[dst] = v; wsm[dst + 1] = v;
        }
    }
    // row offset LUT
    if (tid < TZD*TYD) {
        int zz = tid / TYD, yy = tid - zz*TYD;
        int gz = d0 - 1 + zz, gy = h0 - 1 + yy;
        bool ok = ((unsigned)gz < 16u) && ((unsigned)gy < 64u);
        rowoff[tid] = ok ? ((gz*64 + gy)*64) : -1;
    }
    // permanent zero halos at idx 3 (gx=-1) and 68 (gx=64), both buffers
    for (int idx = tid; idx < TZD*TYD*2*2; idx += 128) {
        int b2 = idx & 1; int r2 = idx >> 1; int side = r2 & 1; int row = r2 >> 1;
        tile[b2][row*TROW + (side ? 68 : 3)] = 0.f;
    }
    __syncthreads();

    int ch16 = tid & 15;                   // 16B chunk within row (floats 4*ch16..+3)
    int rbase = tid >> 4;                  // 0..7
    unsigned dstb = (unsigned)__cvta_generic_to_shared(&tile[0][0])
                  + (unsigned)((rbase*TROW + 4 + ch16*4) * 4);

#define FILL(BSEL, CPTR) do {                                                  \
    unsigned _db = dstb + (unsigned)((BSEL)*(TSIZE*4));                        \
    _Pragma("unroll")                                                          \
    for (int _k = 0; _k < 9; _k++) {                                           \
        int _ro = rowoff[rbase + 8*_k];                                        \
        int _sz = (_ro < 0) ? 0 : 16;                                          \
        const float* _sp = (CPTR) + ((_ro < 0) ? 0 : _ro) + ch16*4;            \
        asm volatile("cp.async.ca.shared.global [%0], [%1], 16, %2;"           \
            :: "r"(_db + (unsigned)(_k*(8*TROW*4))), "l"(_sp), "r"(_sz));      \
    }                                                                          \
    asm volatile("cp.async.commit_group;" ::: "memory");                       \
} while (0)

// apply one (kd,kh) pair-set P[9] against the row pairs, into acc slice DLOC
#define DO_APPLY(P, DLOC) do {                                                 \
    _Pragma("unroll")                                                          \
    for (int o = 0; o < 3; o++) {                                              \
        FMA2(acc[(DLOC)*12 + 0 + o], O0, (P)[o]);                              \
        FMA2(acc[(DLOC)*12 + 3 + o], O1, (P)[o]);                              \
        FMA2(acc[(DLOC)*12 + 6 + o], O2, (P)[o]);                              \
        FMA2(acc[(DLOC)*12 + 9 + o], O3, (P)[o]);                              \
        FMA2(acc[(DLOC)*12 + 0 + o], E0, (P)[3 + o]);                          \
        FMA2(acc[(DLOC)*12 + 3 + o], E1, (P)[3 + o]);                          \
        FMA2(acc[(DLOC)*12 + 6 + o], E2, (P)[3 + o]);                          \
        FMA2(acc[(DLOC)*12 + 9 + o], E3, (P)[3 + o]);                          \
        FMA2(acc[(DLOC)*12 + 0 + o], O1, (P)[6 + o]);                          \
        FMA2(acc[(DLOC)*12 + 3 + o], O2, (P)[6 + o]);                          \
        FMA2(acc[(DLOC)*12 + 6 + o], O3, (P)[6 + o]);                          \
        FMA2(acc[(DLOC)*12 + 9 + o], O4, (P)[6 + o]);                          \
    }                                                                          \
} while (0)

    const float* cptr = inb;
    FILL(0, cptr);

    unsigned long long acc[24];
    #pragma unroll
    for (int j = 0; j < 24; j++) acc[j] = 0ULL;

    for (int c = 0; c < GC; c++) {
        if (c < GC - 1) {
            FILL((c + 1) & 1, cptr + PX);
            asm volatile("cp.async.wait_group 1;" ::: "memory");
        } else {
            asm volatile("cp.async.wait_group 0;" ::: "memory");
        }
        __syncthreads();
        const float* tb = tile[c & 1];
        const float* wch = wsm + c*180;
        #pragma unroll
        for (int kh = 0; kh < 3; kh++) {
            unsigned long long WP[2][9];
            #pragma unroll
            for (int zz = 0; zz < 4; zz++) {
                const float* rowp = tb + (zz*TYD + ty + kh)*TROW + 8*tx;
                F2U Hh, Tt; F4U Bq, Cq;
                Hh.f = *(const float2*)(rowp + 2);   // gx (8tx-2, 8tx-1)
                Bq.f = *(const float4*)(rowp + 4);   // gx 8tx+0..3
                Cq.f = *(const float4*)(rowp + 8);   // gx 8tx+4..7
                Tt.f = *(const float2*)(rowp + 12);  // gx (8tx+8, 8tx+9)
                unsigned long long O0, O1, O2, O3, O4;
                asm("mov.b64 %0, {%1,%2};" : "=l"(O0) : "f"(Hh.f.y), "f"(Bq.f.x));
                asm("mov.b64 %0, {%1,%2};" : "=l"(O1) : "f"(Bq.f.y), "f"(Bq.f.z));
                asm("mov.b64 %0, {%1,%2};" : "=l"(O2) : "f"(Bq.f.w), "f"(Cq.f.x));
                asm("mov.b64 %0, {%1,%2};" : "=l"(O3) : "f"(Cq.f.y), "f"(Cq.f.z));
                asm("mov.b64 %0, {%1,%2};" : "=l"(O4) : "f"(Cq.f.w), "f"(Tt.f.x));
                unsigned long long E0 = Bq.u[0], E1 = Bq.u[1], E2 = Cq.u[0], E3 = Cq.u[1];
                if (zz < 3) {
                    const float* wr = wch + (zz*3 + kh)*20;
                    F4U w0, w1, w2, w3; F2U w4;
                    w0.f = *(const float4*)(wr);
                    w1.f = *(const float4*)(wr + 4);
                    w2.f = *(const float4*)(wr + 8);
                    w3.f = *(const float4*)(wr + 12);
                    w4.f = *(const float2*)(wr + 16);
                    WP[zz & 1][0] = w0.u[0]; WP[zz & 1][1] = w0.u[1];
                    WP[zz & 1][2] = w1.u[0]; WP[zz & 1][3] = w1.u[1];
                    WP[zz & 1][4] = w2.u[0]; WP[zz & 1][5] = w2.u[1];
                    WP[zz & 1][6] = w3.u[0]; WP[zz & 1][7] = w3.u[1];
                    WP[zz & 1][8] = w4.u;
                }
                if (zz <= 2) DO_APPLY(WP[zz & 1], 0);        // kd = zz -> d0
                if (zz >= 1) DO_APPLY(WP[(zz - 1) & 1], 1);  // kd = zz-1 -> d0+1
            }
        }
        __syncthreads();
        cptr += PX;
    }
#undef FILL
#undef DO_APPLY

    #pragma unroll
    for (int dloc = 0; dloc < 2; dloc++) {
        size_t po = ((size_t)(d0 + dloc)*64 + (h0 + ty))*64 + 8*tx;
        float* fp = g_flowp[g] + (size_t)n*3*PX + po;
        #pragma unroll
        for (int o = 0; o < 3; o++) {
            F2U a0, a1, a2, a3;
            a0.u = acc[dloc*12 + 0 + o]; a1.u = acc[dloc*12 + 3 + o];
            a2.u = acc[dloc*12 + 6 + o]; a3.u = acc[dloc*12 + 9 + o];
            *(float4*)(fp + (size_t)o*PX)     = make_float4(a0.f.x, a0.f.y, a1.f.x, a1.f.y);
            *(float4*)(fp + (size_t)o*PX + 4) = make_float4(a2.f.x, a2.f.y, a3.f.x, a3.f.y);
        }
    }
}

// ------------- K5: sum the 16 partial flows into g_flow --------------------
__global__ void k_fsum() {
    int i = blockIdx.x*256 + threadIdx.x;       // over NB*3*PX/4
    float4 s = make_float4(0.f, 0.f, 0.f, 0.f);
    #pragma unroll
    for (int gg = 0; gg < 16; gg++) {
        float4 v = *(const float4*)&g_flowp[gg][(size_t)i*4];
        s.x += v.x; s.y += v.y; s.z += v.z; s.w += v.w;
    }
    *(float4*)&g_flow[(size_t)i*4] = s;
}

// -------- K6: flow warp + grid sample, channel-interleaved lanes ------------
// 4 threads per voxel; lane cg handles channels {cg*4 + 16j + s}.
__global__ void k_sample(float* __restrict__ out) {
    int tid = threadIdx.x;                    // 256
    int q  = tid >> 2;                        // voxel within block (0..63)
    int cg = tid & 3;                         // channel sub-lane
    int p = blockIdx.x*64 + q;                // 0..65535
    int n = blockIdx.y;
    int w = p & 63, h = (p >> 6) & 63, d = p >> 12;

    size_t fo = (size_t)n*3*PX + p;
    float f0 = g_flow[fo];
    float f1 = g_flow[fo + PX];
    float f2 = g_flow[fo + 2*PX];

    float gx = (w + f0) * (1.f/64.f);
    float gy = (h + f1) * (1.f/64.f);
    float gz = (d + f2) * (1.f/16.f);
    float ix = ((gx + 1.f)*32.f - 1.f)*0.5f;
    float iy = ((gy + 1.f)*32.f - 1.f)*0.5f;
    float iz = ((gz + 1.f)*8.f  - 1.f)*0.5f;
    float fx0 = floorf(ix), fy0 = floorf(iy), fz0 = floorf(iz);
    int x0 = (int)fx0, y0 = (int)fy0, z0 = (int)fz0;
    float fx = ix - fx0, fy = iy - fy0, fz = iz - fz0;
    float wx0 = 1.f - fx, wy0 = 1.f - fy, wz0 = 1.f - fz;

    int x0c = min(max(x0, 0), 31), x1c = min(max(x0 + 1, 0), 31);
    int y0c = min(max(y0, 0), 31), y1c = min(max(y0 + 1, 0), 31);
    int z0c = min(max(z0, 0), 7),  z1c = min(max(z0 + 1, 0), 7);
    bool vx0 = ((unsigned)x0 < 32u), vx1 = ((unsigned)(x0 + 1) < 32u);
    bool vy0 = ((unsigned)y0 < 32u), vy1 = ((unsigned)(y0 + 1) < 32u);
    bool vz0 = ((unsigned)z0 < 8u),  vz1 = ((unsigned)(z0 + 1) < 8u);

    int o[8];
    o[0] = (z0c*32 + y0c)*32 + x0c;
    o[1] = (z0c*32 + y0c)*32 + x1c;
    o[2] = (z0c*32 + y1c)*32 + x0c;
    o[3] = (z0c*32 + y1c)*32 + x1c;
    o[4] = (z1c*32 + y0c)*32 + x0c;
    o[5] = (z1c*32 + y0c)*32 + x1c;
    o[6] = (z1c*32 + y1c)*32 + x0c;
    o[7] = (z1c*32 + y1c)*32 + x1c;
    float t[8];
    t[0] = (vz0 && vy0 && vx0) ? wz0*wy0*wx0 : 0.f;
    t[1] = (vz0 && vy0 && vx1) ? wz0*wy0*fx  : 0.f;
    t[2] = (vz0 && vy1 && vx0) ? wz0*fy*wx0  : 0.f;
    t[3] = (vz0 && vy1 && vx1) ? wz0*fy*fx   : 0.f;
    t[4] = (vz1 && vy0 && vx0) ? fz*wy0*wx0  : 0.f;
    t[5] = (vz1 && vy0 && vx1) ? fz*wy0*fx   : 0.f;
    t[6] = (vz1 && vy1 && vx0) ? fz*fy*wx0   : 0.f;
    t[7] = (vz1 && vy1 && vx1) ? fz*fy*fx    : 0.f;

    // lane cg covers channels cg*4 + 16j + s  (s=0..3), j=0..7
    const float* ytb = g_yT + ((size_t)n*PY)*CYC + cg*4;
    unsigned long long acc[16];
    #pragma unroll
    for (int j = 0; j < 16; j++) acc[j] = 0ULL;
    #pragma unroll
    for (int i = 0; i < 8; i++) {
        const float4* tp = (const float4*)(ytb + (size_t)o[i]*CYC);
        F2U tw; tw.f = make_float2(t[i], t[i]);
        #pragma unroll
        for (int j = 0; j < 8; j++) {
            F4U v; v.f = __ldg(tp + j*4);
            FMA2(acc[2*j],     v.u[0], tw.u);
            FMA2(acc[2*j + 1], v.u[1], tw.u);
        }
    }
    float* ob = out + (size_t)n*CYC*PX + (size_t)(cg*4)*PX + p;
    #pragma unroll
    for (int j = 0; j < 8; j++) {
        F2U a, b2; a.u = acc[2*j]; b2.u = acc[2*j + 1];
        ob[(size_t)(16*j + 0)*PX] = a.f.x;
        ob[(size_t)(16*j + 1)*PX] = a.f.y;
        ob[(size_t)(16*j + 2)*PX] = b2.f.x;
        ob[(size_t)(16*j + 3)*PX] = b2.f.y;
    }
}

// --------------------------------- launch ----------------------------------
extern "C" void kernel_launch(void* const* d_in, const int* in_sizes, int n_in,
                              void* d_out, int out_size) {
    const float* x     = (const float*)d_in[0];
    const float* y     = (const float*)d_in[1];
    const float* wdh   = (const float*)d_in[2];
    const float* wdl   = (const float*)d_in[3];
    const float* wflow = (const float*)d_in[4];
    const float* wa    = (const float*)d_in[5];
    const float* wc    = (const float*)d_in[6];
    float* out = (float*)d_out;

    k_pre<<<2432, 256>>>(y, wdh, x);
    k_prep<<<NB, 256>>>(wdl, wa, wc, wflow);
    k_up<<<(NB*CO*PX/4)/256, 256>>>();
    k_conv3<<<dim3(4, 8, NB*16), 128>>>(x, wflow);
    k_fsum<<<(NB*3*PX/4)/256, 256>>>();
    k_sample<<<dim3(PX/64, NB), 256>>>(out);
}

// round 9
// speedup vs baseline: 1.0248x; 1.0248x over previous
#include <cuda_runtime.h>
#include <math.h>

#define NB 2
#define CXC 64
#define CYC 128
#define CO  64
#define DD  16
#define HH  64
#define WW  64
#define PX  (DD*HH*WW)    /* 65536 */
#define PY  (8*32*32)     /* 8192  */

// packed f32x2 FMA (Blackwell): one instr = 2 fp32 FMA
#define FMA2(acc, a, b) asm("fma.rn.f32x2 %0, %1, %2, %0;" : "+l"(acc) : "l"(a), "l"(b))

union F2U { float2 f; unsigned long long u; };
union F4U { float4 f; unsigned long long u[2]; };

// ---------------- scratch (device globals; no allocation) ----------------
__device__ float g_xmean[NB*CXC];
__device__ float g_w1[NB*64*108];                // folded x-path weights [n][i][row][12]
__device__ float g_hf[NB*CO*PY];                 // 4 MB
__device__ float g_hfup[(size_t)NB*CO*PX];       // 33 MB
__device__ float g_flowp[8][NB*3*PX];            // partial flows per 16-ch group
__device__ float g_flow[NB*3*PX];                // summed flow
__device__ float g_yT[(size_t)NB*PY*CYC];        // 8 MB  y transposed to [n][p][c]

// ===== K1 (fused): hf 1x1 conv  |  xmean  |  y transpose ====================
__global__ void k_pre(const float* __restrict__ y,
                      const float* __restrict__ wdh,
                      const float* __restrict__ x) {
    __shared__ float sh[2112];
    int b = blockIdx.x;
    int tid = threadIdx.x;                       // 256

    if (b < 256) {
        int n  = b >> 7;
        int r  = b & 127;
        int og = r >> 5;
        int pb = r & 31;
        float (*wT)[16] = (float(*)[16])sh;      // wT[i][o_local]
        for (int idx = tid; idx < 128*16; idx += 256) {
            int ol = idx >> 7, i = idx & 127;
            wT[i][ol] = wdh[(og*16 + ol)*128 + i];
        }
        __syncthreads();
        int p = pb*256 + tid;
        const float* yp = y + (size_t)n*CYC*PY + p;
        float acc[16];
        #pragma unroll
        for (int o = 0; o < 16; o++) acc[o] = 0.f;
        for (int i = 0; i < 128; i++) {
            float v = yp[(size_t)i*PY];
            #pragma unroll
            for (int o4 = 0; o4 < 4; o4++) {
                float4 w4 = *(const float4*)&wT[i][o4*4];
                acc[o4*4+0] = fmaf(w4.x, v, acc[o4*4+0]);
                acc[o4*4+1] = fmaf(w4.y, v, acc[o4*4+1]);
                acc[o4*4+2] = fmaf(w4.z, v, acc[o4*4+2]);
                acc[o4*4+3] = fmaf(w4.w, v, acc[o4*4+3]);
            }
        }
        float* op = g_hf + (size_t)(n*CO + og*16)*PY + p;
        #pragma unroll
        for (int o = 0; o < 16; o++) op[(size_t)o*PY] = acc[o];
    } else if (b < 384) {
        int nc = b - 256;
        const float4* p4 = (const float4*)(x + (size_t)nc * PX);
        float s = 0.f;
        #pragma unroll 4
        for (int i = tid; i < PX/4; i += 256) {
            float4 v = p4[i];
            s += (v.x + v.y) + (v.z + v.w);
        }
        #pragma unroll
        for (int o = 16; o > 0; o >>= 1) s += __shfl_xor_sync(0xffffffffu, s, o);
        if ((tid & 31) == 0) sh[tid >> 5] = s;
        __syncthreads();
        if (tid < 8) {
            float t = sh[tid];
            #pragma unroll
            for (int o = 4; o > 0; o >>= 1) t += __shfl_xor_sync(0xffu, t, o, 8);
            if (tid == 0) g_xmean[nc] = t * (1.f / PX);
        }
    } else {
        int bb = b - 384;                        // 0..2047
        int n  = bb >> 10;
        int r  = bb & 1023;
        int pt = r >> 2;                         // 0..255
        int ct = r & 3;                          // 0..3
        int tx = tid & 31, ty = tid >> 5;        // ty 0..7
        const float* yb = y + (size_t)n*CYC*PY;
        #pragma unroll
        for (int k = 0; k < 4; k++) {
            int cl = ty + k*8;
            sh[cl*33 + tx] = yb[(size_t)(ct*32 + cl)*PY + pt*32 + tx];
        }
        __syncthreads();
        float* ob = g_yT + ((size_t)n*PY)*CYC;
        #pragma unroll
        for (int k = 0; k < 4; k++) {
            int pl = ty + k*8;
            ob[(size_t)(pt*32 + pl)*CYC + ct*32 + tx] = sh[tx*33 + pl];
        }
    }
}

// ---- K2: fold SE attention + 1x1 conv + flow-conv low half into W1_n ----
// scalar layout: [n][i][row(kd*3+kh)][12], slot kw*3+o3
__global__ void k_prep(const float* __restrict__ wdl,
                       const float* __restrict__ wa,
                       const float* __restrict__ wc,
                       const float* __restrict__ wflow) {
    int n = blockIdx.x, t = threadIdx.x;     // 256 threads
    __shared__ float xm[64], pooled[64], scale[64];
    __shared__ float M[64][64];
    if (t < 64) xm[t] = g_xmean[n*64 + t];
    __syncthreads();
    if (t < 64) {
        float s = 0.f;
        for (int i = 0; i < 64; i++) s += wdl[t*64 + i] * xm[i];
        pooled[t] = s;
    }
    __syncthreads();
    if (t < 64) {
        float a = 0.f;
        for (int i = 0; i < 64; i++) a += wa[t*64 + i] * pooled[i];
        scale[t] = 1.f + 1.f / (1.f + expf(-a));
    }
    __syncthreads();
    for (int idx = t; idx < 4096; idx += 256) {
        int o = idx >> 6, i = idx & 63;
        float acc = 0.f;
        for (int c = 0; c < 64; c++) acc += wc[o*64 + c] * scale[c] * wdl[c*64 + i];
        M[o][i] = acc;
    }
    __syncthreads();
    for (int idx = t; idx < 64*81; idx += 256) {
        int i = idx / 81; int r = idx % 81; int tap = r / 3; int o3 = r % 3;
        float acc = 0.f;
        for (int c = 0; c < 64; c++)
            acc += wflow[o3*(128*27) + (64 + c)*27 + tap] * M[c][i];
        int kd = tap/9, kh = (tap/3)%3, kw = tap%3;
        g_w1[(size_t)(n*64 + i)*108 + (kd*3 + kh)*12 + (kw*3 + o3)] = acc;
    }
}

// ------ K3: trilinear upsample, 4 outputs/thread, shared source columns ----
__global__ void k_up() {
    int t = blockIdx.x*256 + threadIdx.x;    // over NB*CO*16*64*16
    int wg = (t & 15) << 2;                  // w start: 0,4,...,60
    int h  = (t >> 4) & 63;
    int d  = (t >> 10) & 15;
    int slab = t >> 14;                      // n*CO + c
    const float* hp = g_hf + (size_t)slab * PY;
    float ph = h * (31.f/63.f);
    float pd = d * (7.f/15.f);
    int h0 = (int)ph; float fh = ph - (float)h0; int h1 = min(h0 + 1, 31);
    int d0 = (int)pd; float fd = pd - (float)d0; int d1 = min(d0 + 1, 7);
    int xbase = (int)(wg * (31.f/63.f));
    const float* p00 = hp + (d0*32 + h0)*32;
    const float* p01 = hp + (d0*32 + h1)*32;
    const float* p10 = hp + (d1*32 + h0)*32;
    const float* p11 = hp + (d1*32 + h1)*32;
    float V[4];
    #pragma unroll
    for (int c2 = 0; c2 < 4; c2++) {
        int xc = min(xbase + c2, 31);
        float v00 = __ldg(p00 + xc), v01 = __ldg(p01 + xc);
        float v10 = __ldg(p10 + xc), v11 = __ldg(p11 + xc);
        float a = v00 + (v01 - v00)*fh;
        float b2 = v10 + (v11 - v10)*fh;
        V[c2] = a + (b2 - a)*fd;
    }
    float4 ov;
    float* po = (float*)&ov;
    #pragma unroll
    for (int i = 0; i < 4; i++) {
        float pw = (wg + i) * (31.f/63.f);
        int x0 = (int)pw; float fx = pw - (float)x0;
        int k = x0 - xbase;
        float va = (k == 0) ? V[0] : ((k == 1) ? V[1] : V[2]);
        float vb = (k == 0) ? V[1] : ((k == 1) ? V[2] : V[3]);
        po[i] = va + (vb - va)*fx;
    }
    *(float4*)(g_hfup + (size_t)slab*PX + ((d << 6) + h)*64 + wg) = ov;
}

// ------------- K4: 3x3x3 conv, f32x2, tile d=4 h=8 w=64, GC=16 -------------
// block 128 = (tx 8, ty 8, tz 2); each thread: 2 d x 8 w outputs.
// smem tile 6 x 10 x 72 (gx stored at gx+4; cols 3 and 68 permanent zeros).
#define TROW 72
#define TYD  10
#define TZD  6
#define TSIZE (TZD*TYD*TROW)   /* 4320 */
#define NCHUNK (TZD*TYD*16)    /* 960 16B-chunks per buffer */
#define GC 16                  /* channels per group */
__global__ void __launch_bounds__(128, 4) k_conv3(const float* __restrict__ x,
                                                  const float* __restrict__ wflow) {
    __shared__ __align__(16) float tile[2][TSIZE];
    __shared__ __align__(16) float wsm[GC*108];
    __shared__ int rowoff[TZD*TYD];
    int bz = blockIdx.z;
    int n = bz >> 3, g = bz & 7;
    int d0 = blockIdx.y * 4;
    int h0 = blockIdx.x * 8;
    int tid = threadIdx.x;                 // 0..127
    int tx = tid & 7, ty = (tid >> 3) & 7, tz = tid >> 6;
    int tz2 = tz * 2;

    const float* inb = (g < 4) ? (x + (size_t)(n*64 + g*GC)*PX)
                               : (g_hfup + (size_t)(n*64 + (g-4)*GC)*PX);
    // stage weights: scalar layout [ch][row(kd*3+kh)][12] (slots 0..8 used)
    if (g < 4) {
        const float* src = g_w1 + (size_t)(n*64 + g*GC)*108;
        for (int idx = tid; idx < GC*108; idx += 128) wsm[idx] = src[idx];
    } else {
        int cbase = (g - 4)*GC;
        for (int idx = tid; idx < GC*81; idx += 128) {
            int ch = idx / 81; int r = idx % 81; int tap = r / 3; int o = r % 3;
            int kd = tap/9, kh = (tap/3)%3, kw = tap%3;
            wsm[ch*108 + (kd*3 + kh)*12 + kw*3 + o] =
                wflow[o*(128*27) + (cbase + ch)*27 + tap];
        }
    }
    // row offset LUT (60 rows)
    if (tid < TZD*TYD) {
        int zz = tid / TYD, yy = tid - zz*TYD;
        int gz = d0 - 1 + zz, gy = h0 - 1 + yy;
        bool ok = ((unsigned)gz < 16u) && ((unsigned)gy < 64u);
        rowoff[tid] = ok ? ((gz*64 + gy)*64) : -1;
    }
    // permanent zero halos at col 3 (gx=-1) and 68 (gx=64), both buffers
    for (int idx = tid; idx < TZD*TYD*2*2; idx += 128) {
        int b2 = idx & 1; int r2 = idx >> 1; int side = r2 & 1; int row = r2 >> 1;
        tile[b2][row*TROW + (side ? 68 : 3)] = 0.f;
    }
    __syncthreads();

    // precompute fill slots: chunk e = tid + k*128, row = e>>4, c16 = e&15
    int goff[8];
    unsigned dsto[8];
    unsigned sbase = (unsigned)__cvta_generic_to_shared(&tile[0][0]);
    #pragma unroll
    for (int k = 0; k < 8; k++) {
        int e = tid + k*128;
        if (e < NCHUNK) {
            int row = e >> 4, c16 = e & 15;
            int ro = rowoff[row];
            goff[k] = (ro < 0) ? -1 : (ro + c16*4);
            dsto[k] = sbase + (unsigned)((row*TROW + 4 + c16*4) * 4);
        } else {
            goff[k] = -1; dsto[k] = 0;
        }
    }
    bool live7 = (tid + 7*128) < NCHUNK;   // tid < 64

#define FILL(BSEL, CPTR) do {                                                  \
    unsigned _bo = (unsigned)((BSEL)*(TSIZE*4));                               \
    _Pragma("unroll")                                                          \
    for (int _k = 0; _k < 7; _k++) {                                           \
        int _go = goff[_k];                                                    \
        int _sz = (_go < 0) ? 0 : 16;                                          \
        const float* _sp = (CPTR) + ((_go < 0) ? 0 : _go);                     \
        asm volatile("cp.async.ca.shared.global [%0], [%1], 16, %2;"           \
            :: "r"(dsto[_k] + _bo), "l"(_sp), "r"(_sz));                       \
    }                                                                          \
    if (live7) {                                                               \
        int _go = goff[7];                                                     \
        int _sz = (_go < 0) ? 0 : 16;                                          \
        const float* _sp = (CPTR) + ((_go < 0) ? 0 : _go);                     \
        asm volatile("cp.async.ca.shared.global [%0], [%1], 16, %2;"           \
            :: "r"(dsto[7] + _bo), "l"(_sp), "r"(_sz));                        \
    }                                                                          \
    asm volatile("cp.async.commit_group;" ::: "memory");                       \
} while (0)

// one (kd,kh) weight row against the 5 data pairs, into acc slice DLOC
#define DO_KD(KD, DLOC) do {                                                   \
    const float* wr = wch + ((KD)*3 + kh)*12;                                  \
    F4U W0, W1, W2;                                                            \
    W0.f = *(const float4*)wr;                                                 \
    W1.f = *(const float4*)(wr + 4);                                           \
    W2.f = *(const float4*)(wr + 8);                                           \
    unsigned long long WP[9];                                                  \
    asm("mov.b64 %0, {%1,%1};" : "=l"(WP[0]) : "f"(W0.f.x));                   \
    asm("mov.b64 %0, {%1,%1};" : "=l"(WP[1]) : "f"(W0.f.y));                   \
    asm("mov.b64 %0, {%1,%1};" : "=l"(WP[2]) : "f"(W0.f.z));                   \
    asm("mov.b64 %0, {%1,%1};" : "=l"(WP[3]) : "f"(W0.f.w));                   \
    asm("mov.b64 %0, {%1,%1};" : "=l"(WP[4]) : "f"(W1.f.x));                   \
    asm("mov.b64 %0, {%1,%1};" : "=l"(WP[5]) : "f"(W1.f.y));                   \
    asm("mov.b64 %0, {%1,%1};" : "=l"(WP[6]) : "f"(W1.f.z));                   \
    asm("mov.b64 %0, {%1,%1};" : "=l"(WP[7]) : "f"(W1.f.w));                   \
    asm("mov.b64 %0, {%1,%1};" : "=l"(WP[8]) : "f"(W2.f.x));                   \
    _Pragma("unroll")                                                          \
    for (int o = 0; o < 3; o++) {                                              \
        FMA2(acc[(DLOC)*12 + 0 + o], O0, WP[o]);                               \
        FMA2(acc[(DLOC)*12 + 3 + o], O1, WP[o]);                               \
        FMA2(acc[(DLOC)*12 + 6 + o], O2, WP[o]);                               \
        FMA2(acc[(DLOC)*12 + 9 + o], O3, WP[o]);                               \
        FMA2(acc[(DLOC)*12 + 0 + o], E0, WP[3 + o]);                           \
        FMA2(acc[(DLOC)*12 + 3 + o], E1, WP[3 + o]);                           \
        FMA2(acc[(DLOC)*12 + 6 + o], E2, WP[3 + o]);                           \
        FMA2(acc[(DLOC)*12 + 9 + o], E3, WP[3 + o]);                           \
        FMA2(acc[(DLOC)*12 + 0 + o], O1, WP[6 + o]);                           \
        FMA2(acc[(DLOC)*12 + 3 + o], O2, WP[6 + o]);                           \
        FMA2(acc[(DLOC)*12 + 6 + o], O3, WP[6 + o]);                           \
        FMA2(acc[(DLOC)*12 + 9 + o], O4, WP[6 + o]);                           \
    }                                                                          \
} while (0)

    const float* cptr = inb;
    FILL(0, cptr);

    unsigned long long acc[24];
    #pragma unroll
    for (int j = 0; j < 24; j++) acc[j] = 0ULL;

    for (int c = 0; c < GC; c++) {
        if (c < GC - 1) {
            FILL((c + 1) & 1, cptr + PX);
            asm volatile("cp.async.wait_group 1;" ::: "memory");
        } else {
            asm volatile("cp.async.wait_group 0;" ::: "memory");
        }
        __syncthreads();
        const float* tb = tile[c & 1];
        const float* wch = wsm + c*108;
        #pragma unroll
        for (int zz = 0; zz < 4; zz++) {
            int plane = tz2 + zz;
            #pragma unroll
            for (int kh = 0; kh < 3; kh++) {
                const float* rowp = tb + (plane*TYD + ty + kh)*TROW + 8*tx;
                F2U Hh, Tt; F4U Bq, Cq;
                Hh.f = *(const float2*)(rowp + 2);   // gx (8tx-2, 8tx-1)
                Bq.f = *(const float4*)(rowp + 4);   // gx 8tx+0..3
                Cq.f = *(const float4*)(rowp + 8);   // gx 8tx+4..7
                Tt.f = *(const float2*)(rowp + 12);  // gx (8tx+8, 8tx+9)
                unsigned long long O0, O1, O2, O3, O4;
                asm("mov.b64 %0, {%1,%2};" : "=l"(O0) : "f"(Hh.f.y), "f"(Bq.f.x));
                asm("mov.b64 %0, {%1,%2};" : "=l"(O1) : "f"(Bq.f.y), "f"(Bq.f.z));
                asm("mov.b64 %0, {%1,%2};" : "=l"(O2) : "f"(Bq.f.w), "f"(Cq.f.x));
                asm("mov.b64 %0, {%1,%2};" : "=l"(O3) : "f"(Cq.f.y), "f"(Cq.f.z));
                asm("mov.b64 %0, {%1,%2};" : "=l"(O4) : "f"(Cq.f.w), "f"(Tt.f.x));
                unsigned long long E0 = Bq.u[0], E1 = Bq.u[1], E2 = Cq.u[0], E3 = Cq.u[1];
                if (zz >= 1) DO_KD(zz - 1, 1);   // feeds output d = dbase+1
                if (zz <= 2) DO_KD(zz, 0);       // feeds output d = dbase+0
            }
        }
        __syncthreads();
        cptr += PX;
    }
#undef FILL
#undef DO_KD

    int dbase = d0 + tz2;
    #pragma unroll
    for (int dloc = 0; dloc < 2; dloc++) {
        size_t po = ((size_t)(dbase + dloc)*64 + (h0 + ty))*64 + 8*tx;
        float* fp = g_flowp[g] + (size_t)n*3*PX + po;
        #pragma unroll
        for (int o = 0; o < 3; o++) {
            F2U a0, a1, a2, a3;
            a0.u = acc[dloc*12 + 0 + o]; a1.u = acc[dloc*12 + 3 + o];
            a2.u = acc[dloc*12 + 6 + o]; a3.u = acc[dloc*12 + 9 + o];
            *(float4*)(fp + (size_t)o*PX)     = make_float4(a0.f.x, a0.f.y, a1.f.x, a1.f.y);
            *(float4*)(fp + (size_t)o*PX + 4) = make_float4(a2.f.x, a2.f.y, a3.f.x, a3.f.y);
        }
    }
}

// ------------- K5: sum the 8 partial flows into g_flow ---------------------
__global__ void k_fsum() {
    int i = blockIdx.x*256 + threadIdx.x;       // over NB*3*PX/4
    float4 s = make_float4(0.f, 0.f, 0.f, 0.f);
    #pragma unroll
    for (int gg = 0; gg < 8; gg++) {
        float4 v = *(const float4*)&g_flowp[gg][(size_t)i*4];
        s.x += v.x; s.y += v.y; s.z += v.z; s.w += v.w;
    }
    *(float4*)&g_flow[(size_t)i*4] = s;
}

// -------- K6: flow warp + grid sample, channel-interleaved lanes ------------
// 4 threads per voxel; lane cg handles channels {cg*4 + 16j + s}.
__global__ void k_sample(float* __restrict__ out) {
    int tid = threadIdx.x;                    // 256
    int q  = tid >> 2;                        // voxel within block (0..63)
    int cg = tid & 3;                         // channel sub-lane
    int p = blockIdx.x*64 + q;                // 0..65535
    int n = blockIdx.y;
    int w = p & 63, h = (p >> 6) & 63, d = p >> 12;

    size_t fo = (size_t)n*3*PX + p;
    float f0 = g_flow[fo];
    float f1 = g_flow[fo + PX];
    float f2 = g_flow[fo + 2*PX];

    float gx = (w + f0) * (1.f/64.f);
    float gy = (h + f1) * (1.f/64.f);
    float gz = (d + f2) * (1.f/16.f);
    float ix = ((gx + 1.f)*32.f - 1.f)*0.5f;
    float iy = ((gy + 1.f)*32.f - 1.f)*0.5f;
    float iz = ((gz + 1.f)*8.f  - 1.f)*0.5f;
    float fx0 = floorf(ix), fy0 = floorf(iy), fz0 = floorf(iz);
    int x0 = (int)fx0, y0 = (int)fy0, z0 = (int)fz0;
    float fx = ix - fx0, fy = iy - fy0, fz = iz - fz0;
    float wx0 = 1.f - fx, wy0 = 1.f - fy, wz0 = 1.f - fz;

    int x0c = min(max(x0, 0), 31), x1c = min(max(x0 + 1, 0), 31);
    int y0c = min(max(y0, 0), 31), y1c = min(max(y0 + 1, 0), 31);
    int z0c = min(max(z0, 0), 7),  z1c = min(max(z0 + 1, 0), 7);
    bool vx0 = ((unsigned)x0 < 32u), vx1 = ((unsigned)(x0 + 1) < 32u);
    bool vy0 = ((unsigned)y0 < 32u), vy1 = ((unsigned)(y0 + 1) < 32u);
    bool vz0 = ((unsigned)z0 < 8u),  vz1 = ((unsigned)(z0 + 1) < 8u);

    int o[8];
    o[0] = (z0c*32 + y0c)*32 + x0c;
    o[1] = (z0c*32 + y0c)*32 + x1c;
    o[2] = (z0c*32 + y1c)*32 + x0c;
    o[3] = (z0c*32 + y1c)*32 + x1c;
    o[4] = (z1c*32 + y0c)*32 + x0c;
    o[5] = (z1c*32 + y0c)*32 + x1c;
    o[6] = (z1c*32 + y1c)*32 + x0c;
    o[7] = (z1c*32 + y1c)*32 + x1c;
    float t[8];
    t[0] = (vz0 && vy0 && vx0) ? wz0*wy0*wx0 : 0.f;
    t[1] = (vz0 && vy0 && vx1) ? wz0*wy0*fx  : 0.f;
    t[2] = (vz0 && vy1 && vx0) ? wz0*fy*wx0  : 0.f;
    t[3] = (vz0 && vy1 && vx1) ? wz0*fy*fx   : 0.f;
    t[4] = (vz1 && vy0 && vx0) ? fz*wy0*wx0  : 0.f;
    t[5] = (vz1 && vy0 && vx1) ? fz*wy0*fx   : 0.f;
    t[6] = (vz1 && vy1 && vx0) ? fz*fy*wx0   : 0.f;
    t[7] = (vz1 && vy1 && vx1) ? fz*fy*fx    : 0.f;

    // lane cg covers channels cg*4 + 16j + s  (s=0..3), j=0..7
    const float* ytb = g_yT + ((size_t)n*PY)*CYC + cg*4;
    unsigned long long acc[16];
    #pragma unroll
    for (int j = 0; j < 16; j++) acc[j] = 0ULL;
    #pragma unroll
    for (int i = 0; i < 8; i++) {
        const float4* tp = (const float4*)(ytb + (size_t)o[i]*CYC);
        F2U tw; tw.f = make_float2(t[i], t[i]);
        #pragma unroll
        for (int j = 0; j < 8; j++) {
            F4U v; v.f = __ldg(tp + j*4);
            FMA2(acc[2*j],     v.u[0], tw.u);
            FMA2(acc[2*j + 1], v.u[1], tw.u);
        }
    }
    float* ob = out + (size_t)n*CYC*PX + (size_t)(cg*4)*PX + p;
    #pragma unroll
    for (int j = 0; j < 8; j++) {
        F2U a, b2; a.u = acc[2*j]; b2.u = acc[2*j + 1];
        ob[(size_t)(16*j + 0)*PX] = a.f.x;
        ob[(size_t)(16*j + 1)*PX] = a.f.y;
        ob[(size_t)(16*j + 2)*PX] = b2.f.x;
        ob[(size_t)(16*j + 3)*PX] = b2.f.y;
    }
}

// --------------------------------- launch ----------------------------------
extern "C" void kernel_launch(void* const* d_in, const int* in_sizes, int n_in,
                              void* d_out, int out_size) {
    const float* x     = (const float*)d_in[0];
    const float* y     = (const float*)d_in[1];
    const float* wdh   = (const float*)d_in[2];
    const float* wdl   = (const float*)d_in[3];
    const float* wflow = (const float*)d_in[4];
    const float* wa    = (const float*)d_in[5];
    const float* wc    = (const float*)d_in[6];
    float* out = (float*)d_out;

    k_pre<<<2432, 256>>>(y, wdh, x);
    k_prep<<<NB, 256>>>(wdl, wa, wc, wflow);
    k_up<<<(NB*CO*PX/4)/256, 256>>>();
    k_conv3<<<dim3(8, 4, NB*8), 128>>>(x, wflow);
    k_fsum<<<(NB*3*PX/4)/256, 256>>>();
    k_sample<<<dim3(PX/64, NB), 256>>>(out);
}

// round 10
// speedup vs baseline: 1.0528x; 1.0274x over previous
#include <cuda_runtime.h>
#include <math.h>

#define NB 2
#define CXC 64
#define CYC 128
#define CO  64
#define DD  16
#define HH  64
#define WW  64
#define PX  (DD*HH*WW)    /* 65536 */
#define PY  (8*32*32)     /* 8192  */

// packed f32x2 FMA (Blackwell): one instr = 2 fp32 FMA
#define FMA2(acc, a, b) asm("fma.rn.f32x2 %0, %1, %2, %0;" : "+l"(acc) : "l"(a), "l"(b))

union F2U { float2 f; unsigned long long u; };
union F4U { float4 f; unsigned long long u[2]; };

// ---------------- scratch (device globals; no allocation) ----------------
__device__ float g_xmean[NB*CXC];
__device__ float g_w1[NB*64*108];                // folded x-path weights [n][i][row][12]
__device__ float g_hf[NB*CO*PY];                 // 4 MB
__device__ float g_hfup[(size_t)NB*CO*PX];       // 33 MB
__device__ float g_flowp[16][NB*3*PX];           // partial flows per 8-ch group
__device__ float g_flow[NB*3*PX];                // summed flow
__device__ float g_yT[(size_t)NB*PY*CYC];        // 8 MB  y transposed to [n][p][c]

// ===== K1 (fused): hf 1x1 conv  |  xmean  |  y transpose ====================
__global__ void k_pre(const float* __restrict__ y,
                      const float* __restrict__ wdh,
                      const float* __restrict__ x) {
    __shared__ float sh[2112];
    int b = blockIdx.x;
    int tid = threadIdx.x;                       // 256

    if (b < 256) {
        int n  = b >> 7;
        int r  = b & 127;
        int og = r >> 5;
        int pb = r & 31;
        float (*wT)[16] = (float(*)[16])sh;      // wT[i][o_local]
        for (int idx = tid; idx < 128*16; idx += 256) {
            int ol = idx >> 7, i = idx & 127;
            wT[i][ol] = wdh[(og*16 + ol)*128 + i];
        }
        __syncthreads();
        int p = pb*256 + tid;
        const float* yp = y + (size_t)n*CYC*PY + p;
        float acc[16];
        #pragma unroll
        for (int o = 0; o < 16; o++) acc[o] = 0.f;
        for (int i = 0; i < 128; i++) {
            float v = yp[(size_t)i*PY];
            #pragma unroll
            for (int o4 = 0; o4 < 4; o4++) {
                float4 w4 = *(const float4*)&wT[i][o4*4];
                acc[o4*4+0] = fmaf(w4.x, v, acc[o4*4+0]);
                acc[o4*4+1] = fmaf(w4.y, v, acc[o4*4+1]);
                acc[o4*4+2] = fmaf(w4.z, v, acc[o4*4+2]);
                acc[o4*4+3] = fmaf(w4.w, v, acc[o4*4+3]);
            }
        }
        float* op = g_hf + (size_t)(n*CO + og*16)*PY + p;
        #pragma unroll
        for (int o = 0; o < 16; o++) op[(size_t)o*PY] = acc[o];
    } else if (b < 384) {
        int nc = b - 256;
        const float4* p4 = (const float4*)(x + (size_t)nc * PX);
        float s = 0.f;
        #pragma unroll 4
        for (int i = tid; i < PX/4; i += 256) {
            float4 v = p4[i];
            s += (v.x + v.y) + (v.z + v.w);
        }
        #pragma unroll
        for (int o = 16; o > 0; o >>= 1) s += __shfl_xor_sync(0xffffffffu, s, o);
        if ((tid & 31) == 0) sh[tid >> 5] = s;
        __syncthreads();
        if (tid < 8) {
            float t = sh[tid];
            #pragma unroll
            for (int o = 4; o > 0; o >>= 1) t += __shfl_xor_sync(0xffu, t, o, 8);
            if (tid == 0) g_xmean[nc] = t * (1.f / PX);
        }
    } else {
        int bb = b - 384;                        // 0..2047
        int n  = bb >> 10;
        int r  = bb & 1023;
        int pt = r >> 2;                         // 0..255
        int ct = r & 3;                          // 0..3
        int tx = tid & 31, ty = tid >> 5;        // ty 0..7
        const float* yb = y + (size_t)n*CYC*PY;
        #pragma unroll
        for (int k = 0; k < 4; k++) {
            int cl = ty + k*8;
            sh[cl*33 + tx] = yb[(size_t)(ct*32 + cl)*PY + pt*32 + tx];
        }
        __syncthreads();
        float* ob = g_yT + ((size_t)n*PY)*CYC;
        #pragma unroll
        for (int k = 0; k < 4; k++) {
            int pl = ty + k*8;
            ob[(size_t)(pt*32 + pl)*CYC + ct*32 + tx] = sh[tx*33 + pl];
        }
    }
}

// ---- K2: fold SE attention + 1x1 conv + flow-conv low half into W1_n ----
__global__ void k_prep(const float* __restrict__ wdl,
                       const float* __restrict__ wa,
                       const float* __restrict__ wc,
                       const float* __restrict__ wflow) {
    int n = blockIdx.x, t = threadIdx.x;     // 256 threads
    __shared__ float xm[64], pooled[64], scale[64];
    __shared__ float M[64][64];
    if (t < 64) xm[t] = g_xmean[n*64 + t];
    __syncthreads();
    if (t < 64) {
        float s = 0.f;
        for (int i = 0; i < 64; i++) s += wdl[t*64 + i] * xm[i];
        pooled[t] = s;
    }
    __syncthreads();
    if (t < 64) {
        float a = 0.f;
        for (int i = 0; i < 64; i++) a += wa[t*64 + i] * pooled[i];
        scale[t] = 1.f + 1.f / (1.f + expf(-a));
    }
    __syncthreads();
    for (int idx = t; idx < 4096; idx += 256) {
        int o = idx >> 6, i = idx & 63;
        float acc = 0.f;
        for (int c = 0; c < 64; c++) acc += wc[o*64 + c] * scale[c] * wdl[c*64 + i];
        M[o][i] = acc;
    }
    __syncthreads();
    for (int idx = t; idx < 64*81; idx += 256) {
        int i = idx / 81; int r = idx % 81; int tap = r / 3; int o3 = r % 3;
        float acc = 0.f;
        for (int c = 0; c < 64; c++)
            acc += wflow[o3*(128*27) + (64 + c)*27 + tap] * M[c][i];
        int kd = tap/9, kh = (tap/3)%3, kw = tap%3;
        g_w1[(size_t)(n*64 + i)*108 + (kd*3 + kh)*12 + (kw*3 + o3)] = acc;
    }
}

// ------ K3: trilinear upsample, 4 outputs/thread, shared source columns ----
__global__ void k_up() {
    int t = blockIdx.x*256 + threadIdx.x;    // over NB*CO*16*64*16
    int wg = (t & 15) << 2;                  // w start: 0,4,...,60
    int h  = (t >> 4) & 63;
    int d  = (t >> 10) & 15;
    int slab = t >> 14;                      // n*CO + c
    const float* hp = g_hf + (size_t)slab * PY;
    float ph = h * (31.f/63.f);
    float pd = d * (7.f/15.f);
    int h0 = (int)ph; float fh = ph - (float)h0; int h1 = min(h0 + 1, 31);
    int d0 = (int)pd; float fd = pd - (float)d0; int d1 = min(d0 + 1, 7);
    int xbase = (int)(wg * (31.f/63.f));
    const float* p00 = hp + (d0*32 + h0)*32;
    const float* p01 = hp + (d0*32 + h1)*32;
    const float* p10 = hp + (d1*32 + h0)*32;
    const float* p11 = hp + (d1*32 + h1)*32;
    float V[4];
    #pragma unroll
    for (int c2 = 0; c2 < 4; c2++) {
        int xc = min(xbase + c2, 31);
        float v00 = __ldg(p00 + xc), v01 = __ldg(p01 + xc);
        float v10 = __ldg(p10 + xc), v11 = __ldg(p11 + xc);
        float a = v00 + (v01 - v00)*fh;
        float b2 = v10 + (v11 - v10)*fh;
        V[c2] = a + (b2 - a)*fd;
    }
    float4 ov;
    float* po = (float*)&ov;
    #pragma unroll
    for (int i = 0; i < 4; i++) {
        float pw = (wg + i) * (31.f/63.f);
        int x0 = (int)pw; float fx = pw - (float)x0;
        int k = x0 - xbase;
        float va = (k == 0) ? V[0] : ((k == 1) ? V[1] : V[2]);
        float vb = (k == 0) ? V[1] : ((k == 1) ? V[2] : V[3]);
        po[i] = va + (vb - va)*fx;
    }
    *(float4*)(g_hfup + (size_t)slab*PX + ((d << 6) + h)*64 + wg) = ov;
}

// ------------- K4: 3x3x3 conv (R7 version, best measured) ------------------
// block 128 = (tx 8, ty 16): outputs d0..d0+1, h0..h0+15, w 0..63
// smem tile 4 x 18 x 72 (gx stored at gx+4; idx 3 and 68 permanent zeros).
#define TROW 72
#define TYD  18
#define TZD  4
#define TSIZE (TZD*TYD*TROW)   /* 5184 */
#define GC 8                   /* channels per group */
__global__ void __launch_bounds__(128) k_conv3(const float* __restrict__ x,
                                               const float* __restrict__ wflow) {
    __shared__ __align__(16) float tile[2][TSIZE];
    __shared__ __align__(16) float wsm[GC*108];
    __shared__ int rowoff[TZD*TYD];
    int bz = blockIdx.z;
    int n = bz >> 4, g = bz & 15;
    int d0 = blockIdx.y * 2;
    int h0 = blockIdx.x * 16;
    int tid = threadIdx.x;                 // 0..127
    int tx = tid & 7, ty = tid >> 3;       // ty 0..15

    const float* inb = (g < 8) ? (x + (size_t)(n*64 + g*GC)*PX)
                               : (g_hfup + (size_t)(n*64 + (g-8)*GC)*PX);
    // stage weights: scalar layout [ch][row(kd*3+kh)][12] (slots 0..8 used)
    if (g < 8) {
        const float* src = g_w1 + (size_t)(n*64 + g*GC)*108;
        for (int idx = tid; idx < GC*108; idx += 128) wsm[idx] = src[idx];
    } else {
        int cbase = (g - 8)*GC;
        for (int idx = tid; idx < GC*81; idx += 128) {
            int ch = idx / 81; int r = idx % 81; int tap = r / 3; int o = r % 3;
            int kd = tap/9, kh = (tap/3)%3, kw = tap%3;
            wsm[ch*108 + (kd*3 + kh)*12 + kw*3 + o] =
                wflow[o*(128*27) + (cbase + ch)*27 + tap];
        }
    }
    // row offset LUT
    if (tid < TZD*TYD) {
        int zz = tid / TYD, yy = tid - zz*TYD;
        int gz = d0 - 1 + zz, gy = h0 - 1 + yy;
        bool ok = ((unsigned)gz < 16u) && ((unsigned)gy < 64u);
        rowoff[tid] = ok ? ((gz*64 + gy)*64) : -1;
    }
    // permanent zero halos at idx 3 (gx=-1) and 68 (gx=64), both buffers
    for (int idx = tid; idx < TZD*TYD*2*2; idx += 128) {
        int b2 = idx & 1; int r2 = idx >> 1; int side = r2 & 1; int row = r2 >> 1;
        tile[b2][row*TROW + (side ? 68 : 3)] = 0.f;
    }
    __syncthreads();

    int ch16 = tid & 15;                   // 16B chunk within row (floats 4*ch16..+3)
    int rbase = tid >> 4;                  // 0..7
    unsigned dstb = (unsigned)__cvta_generic_to_shared(&tile[0][0])
                  + (unsigned)((rbase*TROW + 4 + ch16*4) * 4);

#define FILL(BSEL, CPTR) do {                                                  \
    unsigned _db = dstb + (unsigned)((BSEL)*(TSIZE*4));                        \
    _Pragma("unroll")                                                          \
    for (int _k = 0; _k < 9; _k++) {                                           \
        int _ro = rowoff[rbase + 8*_k];                                        \
        int _sz = (_ro < 0) ? 0 : 16;                                          \
        const float* _sp = (CPTR) + ((_ro < 0) ? 0 : _ro) + ch16*4;            \
        asm volatile("cp.async.ca.shared.global [%0], [%1], 16, %2;"           \
            :: "r"(_db + (unsigned)(_k*(8*TROW*4))), "l"(_sp), "r"(_sz));      \
    }                                                                          \
    asm volatile("cp.async.commit_group;" ::: "memory");                       \
} while (0)

// one (kd,kh) weight row against the 5 data pairs, into acc slice DLOC
#define DO_KD(KD, DLOC) do {                                                   \
    const float* wr = wch + ((KD)*3 + kh)*12;                                  \
    F4U W0, W1, W2;                                                            \
    W0.f = *(const float4*)wr;                                                 \
    W1.f = *(const float4*)(wr + 4);                                           \
    W2.f = *(const float4*)(wr + 8);                                           \
    unsigned long long WP[9];                                                  \
    asm("mov.b64 %0, {%1,%1};" : "=l"(WP[0]) : "f"(W0.f.x));                   \
    asm("mov.b64 %0, {%1,%1};" : "=l"(WP[1]) : "f"(W0.f.y));                   \
    asm("mov.b64 %0, {%1,%1};" : "=l"(WP[2]) : "f"(W0.f.z));                   \
    asm("mov.b64 %0, {%1,%1};" : "=l"(WP[3]) : "f"(W0.f.w));                   \
    asm("mov.b64 %0, {%1,%1};" : "=l"(WP[4]) : "f"(W1.f.x));                   \
    asm("mov.b64 %0, {%1,%1};" : "=l"(WP[5]) : "f"(W1.f.y));                   \
    asm("mov.b64 %0, {%1,%1};" : "=l"(WP[6]) : "f"(W1.f.z));                   \
    asm("mov.b64 %0, {%1,%1};" : "=l"(WP[7]) : "f"(W1.f.w));                   \
    asm("mov.b64 %0, {%1,%1};" : "=l"(WP[8]) : "f"(W2.f.x));                   \
    _Pragma("unroll")                                                          \
    for (int o = 0; o < 3; o++) {                                              \
        FMA2(acc[(DLOC)*12 + 0 + o], O0, WP[o]);                               \
        FMA2(acc[(DLOC)*12 + 3 + o], O1, WP[o]);                               \
        FMA2(acc[(DLOC)*12 + 6 + o], O2, WP[o]);                               \
        FMA2(acc[(DLOC)*12 + 9 + o], O3, WP[o]);                               \
        FMA2(acc[(DLOC)*12 + 0 + o], E0, WP[3 + o]);                           \
        FMA2(acc[(DLOC)*12 + 3 + o], E1, WP[3 + o]);                           \
        FMA2(acc[(DLOC)*12 + 6 + o], E2, WP[3 + o]);                           \
        FMA2(acc[(DLOC)*12 + 9 + o], E3, WP[3 + o]);                           \
        FMA2(acc[(DLOC)*12 + 0 + o], O1, WP[6 + o]);                           \
        FMA2(acc[(DLOC)*12 + 3 + o], O2, WP[6 + o]);                           \
        FMA2(acc[(DLOC)*12 + 6 + o], O3, WP[6 + o]);                           \
        FMA2(acc[(DLOC)*12 + 9 + o], O4, WP[6 + o]);                           \
    }                                                                          \
} while (0)

    const float* cptr = inb;
    FILL(0, cptr);

    unsigned long long acc[24];
    #pragma unroll
    for (int j = 0; j < 24; j++) acc[j] = 0ULL;

    for (int c = 0; c < GC; c++) {
        if (c < GC - 1) {
            FILL((c + 1) & 1, cptr + PX);
            asm volatile("cp.async.wait_group 1;" ::: "memory");
        } else {
            asm volatile("cp.async.wait_group 0;" ::: "memory");
        }
        __syncthreads();
        const float* tb = tile[c & 1];
        const float* wch = wsm + c*108;
        #pragma unroll
        for (int zz = 0; zz < 4; zz++) {
            #pragma unroll
            for (int kh = 0; kh < 3; kh++) {
                const float* rowp = tb + (zz*TYD + ty + kh)*TROW + 8*tx;
                F2U Hh, Tt; F4U Bq, Cq;
                Hh.f = *(const float2*)(rowp + 2);   // gx (8tx-2, 8tx-1)
                Bq.f = *(const float4*)(rowp + 4);   // gx 8tx+0..3
                Cq.f = *(const float4*)(rowp + 8);   // gx 8tx+4..7
                Tt.f = *(const float2*)(rowp + 12);  // gx (8tx+8, 8tx+9)
                unsigned long long O0, O1, O2, O3, O4;
                asm("mov.b64 %0, {%1,%2};" : "=l"(O0) : "f"(Hh.f.y), "f"(Bq.f.x));
                asm("mov.b64 %0, {%1,%2};" : "=l"(O1) : "f"(Bq.f.y), "f"(Bq.f.z));
                asm("mov.b64 %0, {%1,%2};" : "=l"(O2) : "f"(Bq.f.w), "f"(Cq.f.x));
                asm("mov.b64 %0, {%1,%2};" : "=l"(O3) : "f"(Cq.f.y), "f"(Cq.f.z));
                asm("mov.b64 %0, {%1,%2};" : "=l"(O4) : "f"(Cq.f.w), "f"(Tt.f.x));
                unsigned long long E0 = Bq.u[0], E1 = Bq.u[1], E2 = Cq.u[0], E3 = Cq.u[1];
                if (zz >= 1) DO_KD(zz - 1, 1);   // input z feeds output d0+1
                if (zz <= 2) DO_KD(zz, 0);       // input z feeds output d0
            }
        }
        __syncthreads();
        cptr += PX;
    }
#undef FILL
#undef DO_KD

    #pragma unroll
    for (int dloc = 0; dloc < 2; dloc++) {
        size_t po = ((size_t)(d0 + dloc)*64 + (h0 + ty))*64 + 8*tx;
        float* fp = g_flowp[g] + (size_t)n*3*PX + po;
        #pragma unroll
        for (int o = 0; o < 3; o++) {
            F2U a0, a1, a2, a3;
            a0.u = acc[dloc*12 + 0 + o]; a1.u = acc[dloc*12 + 3 + o];
            a2.u = acc[dloc*12 + 6 + o]; a3.u = acc[dloc*12 + 9 + o];
            *(float4*)(fp + (size_t)o*PX)     = make_float4(a0.f.x, a0.f.y, a1.f.x, a1.f.y);
            *(float4*)(fp + (size_t)o*PX + 4) = make_float4(a2.f.x, a2.f.y, a3.f.x, a3.f.y);
        }
    }
}

// ------------- K5: sum the 16 partial flows into g_flow --------------------
__global__ void k_fsum() {
    int i = blockIdx.x*256 + threadIdx.x;       // over NB*3*PX/4
    float4 s = make_float4(0.f, 0.f, 0.f, 0.f);
    #pragma unroll
    for (int gg = 0; gg < 16; gg++) {
        float4 v = *(const float4*)&g_flowp[gg][(size_t)i*4];
        s.x += v.x; s.y += v.y; s.z += v.z; s.w += v.w;
    }
    *(float4*)&g_flow[(size_t)i*4] = s;
}

// -------- K6: flow warp + grid sample, 8 lanes/voxel, smem-staged stores ----
// warp = 4 voxels x 8 lanes; lane s reads floats [s*4 + 32j, +4) per tap row
// so each octet load covers one contiguous 128B line.
__global__ void k_sample(float* __restrict__ out) {
    __shared__ float sm[128*33];
    int tid = threadIdx.x;                    // 256
    int q  = tid >> 3;                        // voxel within block (0..31)
    int s  = tid & 7;                         // channel octet lane
    int p = blockIdx.x*32 + q;                // 0..65535
    int n = blockIdx.y;
    int w = p & 63, h = (p >> 6) & 63, d = p >> 12;

    size_t fo = (size_t)n*3*PX + p;
    float f0 = g_flow[fo];
    float f1 = g_flow[fo + PX];
    float f2 = g_flow[fo + 2*PX];

    float gx = (w + f0) * (1.f/64.f);
    float gy = (h + f1) * (1.f/64.f);
    float gz = (d + f2) * (1.f/16.f);
    float ix = ((gx + 1.f)*32.f - 1.f)*0.5f;
    float iy = ((gy + 1.f)*32.f - 1.f)*0.5f;
    float iz = ((gz + 1.f)*8.f  - 1.f)*0.5f;
    float fx0 = floorf(ix), fy0 = floorf(iy), fz0 = floorf(iz);
    int x0 = (int)fx0, y0 = (int)fy0, z0 = (int)fz0;
    float fx = ix - fx0, fy = iy - fy0, fz = iz - fz0;
    float wx0 = 1.f - fx, wy0 = 1.f - fy, wz0 = 1.f - fz;

    int x0c = min(max(x0, 0), 31), x1c = min(max(x0 + 1, 0), 31);
    int y0c = min(max(y0, 0), 31), y1c = min(max(y0 + 1, 0), 31);
    int z0c = min(max(z0, 0), 7),  z1c = min(max(z0 + 1, 0), 7);
    bool vx0 = ((unsigned)x0 < 32u), vx1 = ((unsigned)(x0 + 1) < 32u);
    bool vy0 = ((unsigned)y0 < 32u), vy1 = ((unsigned)(y0 + 1) < 32u);
    bool vz0 = ((unsigned)z0 < 8u),  vz1 = ((unsigned)(z0 + 1) < 8u);

    int o[8];
    o[0] = (z0c*32 + y0c)*32 + x0c;
    o[1] = (z0c*32 + y0c)*32 + x1c;
    o[2] = (z0c*32 + y1c)*32 + x0c;
    o[3] = (z0c*32 + y1c)*32 + x1c;
    o[4] = (z1c*32 + y0c)*32 + x0c;
    o[5] = (z1c*32 + y0c)*32 + x1c;
    o[6] = (z1c*32 + y1c)*32 + x0c;
    o[7] = (z1c*32 + y1c)*32 + x1c;
    float t[8];
    t[0] = (vz0 && vy0 && vx0) ? wz0*wy0*wx0 : 0.f;
    t[1] = (vz0 && vy0 && vx1) ? wz0*wy0*fx  : 0.f;
    t[2] = (vz0 && vy1 && vx0) ? wz0*fy*wx0  : 0.f;
    t[3] = (vz0 && vy1 && vx1) ? wz0*fy*fx   : 0.f;
    t[4] = (vz1 && vy0 && vx0) ? fz*wy0*wx0  : 0.f;
    t[5] = (vz1 && vy0 && vx1) ? fz*wy0*fx   : 0.f;
    t[6] = (vz1 && vy1 && vx0) ? fz*fy*wx0   : 0.f;
    t[7] = (vz1 && vy1 && vx1) ? fz*fy*fx    : 0.f;

    // lane s covers channels s*4 + 32j + e  (e=0..3), j=0..3
    const float* ytb = g_yT + ((size_t)n*PY)*CYC + s*4;
    unsigned long long acc[8];
    #pragma unroll
    for (int j = 0; j < 8; j++) acc[j] = 0ULL;
    #pragma unroll
    for (int i = 0; i < 8; i++) {
        const float4* tp = (const float4*)(ytb + (size_t)o[i]*CYC);
        F2U tw; tw.f = make_float2(t[i], t[i]);
        #pragma unroll
        for (int j = 0; j < 4; j++) {
            F4U v; v.f = __ldg(tp + j*8);       // floats s*4 + 32j .. +3
            FMA2(acc[2*j],     v.u[0], tw.u);
            FMA2(acc[2*j + 1], v.u[1], tw.u);
        }
    }
    // stage into smem (bank-conflict-free: bank = (4s + e + q) mod 32)
    #pragma unroll
    for (int j = 0; j < 4; j++) {
        F2U a, b2; a.u = acc[2*j]; b2.u = acc[2*j + 1];
        int ch = s*4 + 32*j;
        sm[(ch + 0)*33 + q] = a.f.x;
        sm[(ch + 1)*33 + q] = a.f.y;
        sm[(ch + 2)*33 + q] = b2.f.x;
        sm[(ch + 3)*33 + q] = b2.f.y;
    }
    __syncthreads();
    // coalesced write-out: one 128B line per channel row
    int p0 = blockIdx.x*32;
    float* ob = out + (size_t)n*CYC*PX + p0;
    #pragma unroll
    for (int it = 0; it < 16; it++) {
        int idx = it*256 + tid;
        int ch = idx >> 5, v = idx & 31;
        ob[(size_t)ch*PX + v] = sm[ch*33 + v];
    }
}

// --------------------------------- launch ----------------------------------
extern "C" void kernel_launch(void* const* d_in, const int* in_sizes, int n_in,
                              void* d_out, int out_size) {
    const float* x     = (const float*)d_in[0];
    const float* y     = (const float*)d_in[1];
    const float* wdh   = (const float*)d_in[2];
    const float* wdl   = (const float*)d_in[3];
    const float* wflow = (const float*)d_in[4];
    const float* wa    = (const float*)d_in[5];
    const float* wc    = (const float*)d_in[6];
    float* out = (float*)d_out;

    k_pre<<<2432, 256>>>(y, wdh, x);
    k_prep<<<NB, 256>>>(wdl, wa, wc, wflow);
    k_up<<<(NB*CO*PX/4)/256, 256>>>();
    k_conv3<<<dim3(4, 8, NB*16), 128>>>(x, wflow);
    k_fsum<<<(NB*3*PX/4)/256, 256>>>();
    k_sample<<<dim3(PX/32, NB), 256>>>(out);
}